// round 3
// baseline (speedup 1.0000x reference)
#include <cuda_runtime.h>
#include <math.h>

#define BB   8
#define NN   107136
#define PRE  2048
#define POST 128
#define CAND 4096
#define WPB  32      // 64-bit words per row mask (PRE/64)
#define HB   65536   // 16-bit histogram bins

// ---------------- scratch (static __device__, no allocations) ----------------
static __device__ unsigned int       g_skey[BB * NN];
static __device__ unsigned int       g_hist16[BB * HB];
static __device__ unsigned int       g_hist2[BB * HB];
static __device__ unsigned int       g_t16[BB];
static __device__ int                g_target2[BB];
static __device__ unsigned int       g_thresh[BB];
static __device__ unsigned long long g_cand[BB * CAND];
static __device__ int                g_cand_cnt[BB];
static __device__ unsigned long long g_topkeys[BB * PRE];
static __device__ float              g_boxes[BB * PRE * 7];
static __device__ float4             g_bb4[BB * PRE];
static __device__ int                g_dl[BB * PRE];
static __device__ unsigned long long g_supmask[(size_t)BB * PRE * WPB];
static __device__ unsigned long long g_validmask[BB * WPB];
static __device__ unsigned long long g_keepmask[BB * WPB];

// ---------------- 0) zero scratch ----------------
__global__ void zero_kernel() {
    int i = blockIdx.x * blockDim.x + threadIdx.x;
    if (i < BB * HB) { g_hist16[i] = 0u; g_hist2[i] = 0u; }
    if (i < BB) g_cand_cnt[i] = 0;
    if (i < BB * WPB) g_validmask[i] = 0ull;
    if (i < BB * PRE) g_topkeys[i] = 0ull;
}

// ---------------- 1) scores -> keys + top-16 histogram ----------------
__global__ void score_hist_kernel(const float2* __restrict__ cls) {
    int i = blockIdx.x * blockDim.x + threadIdx.x;
    if (i >= BB * NN) return;
    int b = i / NN;
    float2 c = cls[i];
    float m  = fmaxf(c.x, c.y);
    float e0 = expf(c.x - m), e1 = expf(c.y - m);
    float p1 = e1 / (e0 + e1);
    unsigned int k = (p1 >= 0.05f) ? __float_as_uint(p1) : 0u;
    g_skey[i] = k;
    if (k) atomicAdd(&g_hist16[b * HB + (k >> 16)], 1u);
}

// ---------------- 2) find 16-bit prefix (1024 threads) ----------------
__global__ void __launch_bounds__(1024) scan1_kernel() {
    int b = blockIdx.x, tid = threadIdx.x;
    __shared__ unsigned int csum[256];
    if (tid < 256) csum[tid] = 0u;
    __syncthreads();
    const uint4* h4 = (const uint4*)(g_hist16 + b * HB);
    unsigned int s = 0;
    for (int j = 0; j < 16; ++j) {           // 64 bins per thread
        uint4 v = h4[tid * 16 + j];
        s += v.x + v.y + v.z + v.w;
    }
    atomicAdd(&csum[tid >> 2], s);           // chunk = 256 bins = 4 threads
    __syncthreads();
    if (tid == 0) {
        const unsigned int* h = g_hist16 + b * HB;
        int run = 0, chunk = -1;
        for (int c = 255; c >= 0; --c) {
            if (run + (int)csum[c] >= PRE) { chunk = c; break; }
            run += (int)csum[c];
        }
        if (chunk < 0) {
            g_t16[b] = 0xFFFFFFFFu;          // fewer than PRE: take all
            g_thresh[b] = 1u;
        } else {
            for (int v = chunk * 256 + 255; v >= chunk * 256; --v) {
                int cnt = (int)h[v];
                if (run + cnt >= PRE) { g_t16[b] = (unsigned)v; g_target2[b] = PRE - run; break; }
                run += cnt;
            }
        }
    }
}

// ---------------- 3) low-16 histogram within crossing bin ----------------
__global__ void hist2_kernel() {
    int i = blockIdx.x * blockDim.x + threadIdx.x;
    if (i >= BB * NN) return;
    int b = i / NN;
    unsigned int t16 = g_t16[b];
    unsigned int k = g_skey[i];
    if (k && (k >> 16) == t16)
        atomicAdd(&g_hist2[b * HB + (k & 0xFFFFu)], 1u);
}

// ---------------- 4) resolve exact 32-bit threshold (1024 threads) ----------
__global__ void __launch_bounds__(1024) scan2_kernel() {
    int b = blockIdx.x, tid = threadIdx.x;
    __shared__ unsigned int csum[256];
    if (g_t16[b] == 0xFFFFFFFFu) return;
    if (tid < 256) csum[tid] = 0u;
    __syncthreads();
    const uint4* h4 = (const uint4*)(g_hist2 + b * HB);
    unsigned int s = 0;
    for (int j = 0; j < 16; ++j) {
        uint4 v = h4[tid * 16 + j];
        s += v.x + v.y + v.z + v.w;
    }
    atomicAdd(&csum[tid >> 2], s);
    __syncthreads();
    if (tid == 0) {
        const unsigned int* h = g_hist2 + b * HB;
        int target = g_target2[b];
        int run = 0, chunk = 255;
        for (int c = 255; c >= 0; --c) {
            if (run + (int)csum[c] >= target) { chunk = c; break; }
            run += (int)csum[c];
        }
        unsigned int lo = 0;
        for (int v = chunk * 256 + 255; v >= chunk * 256; --v) {
            int cnt = (int)h[v];
            if (run + cnt >= target) { lo = (unsigned)v; break; }
            run += cnt;
        }
        g_thresh[b] = (g_t16[b] << 16) | lo;
    }
}

// ---------------- 5) compact candidates ----------------
__global__ void compact_kernel() {
    int i = blockIdx.x * blockDim.x + threadIdx.x;
    if (i >= BB * NN) return;
    int b = i / NN;
    unsigned int k = g_skey[i];
    if (k && k >= g_thresh[b]) {
        int pos = atomicAdd(&g_cand_cnt[b], 1);
        if (pos < CAND) {
            unsigned int n = (unsigned)(i - b * NN);
            g_cand[b * CAND + pos] = ((unsigned long long)k << 32) |
                                     (unsigned long long)(0xFFFFFFFFu - n);
        }
    }
}

// ---------------- 6) rank-scatter: exact top-2048 order, no sort ------------
__global__ void __launch_bounds__(256) rank_kernel() {
    int b = blockIdx.y, tid = threadIdx.x;
    __shared__ unsigned long long sk[CAND];
    int cnt = g_cand_cnt[b]; if (cnt > CAND) cnt = CAND;
    for (int i = tid; i < CAND; i += 256)
        sk[i] = (i < cnt) ? g_cand[b * CAND + i] : 0ull;
    __syncthreads();
    int i = blockIdx.x * 256 + tid;
    if (i >= cnt) return;
    unsigned long long mine = sk[i];
    int rank = 0;
#pragma unroll 8
    for (int j = 0; j < CAND; ++j)
        rank += (sk[j] > mine) ? 1 : 0;
    if (rank < PRE)
        g_topkeys[(size_t)b * PRE + rank] = mine;
}

// ---------------- 7) decode selected boxes ----------------
__global__ void decode_kernel(const float* __restrict__ boxp,
                              const float* __restrict__ dirp,
                              const float* __restrict__ anch) {
    int i = blockIdx.x * blockDim.x + threadIdx.x;
    if (i >= BB * PRE) return;
    int b = i / PRE, r = i % PRE;
    unsigned long long key = g_topkeys[i];
    unsigned int skey = (unsigned)(key >> 32);

    float o[7] = {0.f, 0.f, 0.f, 0.f, 0.f, 0.f, 0.f};
    float4 bb  = make_float4(0.f, 0.f, 0.f, 0.f);
    int dl = 0;

    if (skey) {
        unsigned idx = 0xFFFFFFFFu - (unsigned)(key & 0xFFFFFFFFull);
        size_t base = ((size_t)b * NN + idx) * 7;
        float xa = anch[base + 0], ya = anch[base + 1], za = anch[base + 2];
        float wa = anch[base + 3], la = anch[base + 4], ha = anch[base + 5];
        float ra = anch[base + 6];
        float xt = boxp[base + 0], yt = boxp[base + 1], zt = boxp[base + 2];
        float wt = boxp[base + 3], lt = boxp[base + 4], ht = boxp[base + 5];
        float rt = boxp[base + 6];

        za = za + ha * 0.5f;
        float diag = sqrtf(la * la + wa * wa);
        float xg = xt * diag + xa;
        float yg = yt * diag + ya;
        float zg = zt * ha + za;
        float lg = expf(lt) * la;
        float wg = expf(wt) * wa;
        float hg = expf(ht) * ha;
        float rg = rt + ra;
        zg = zg - hg * 0.5f;

        o[0] = xg; o[1] = yg; o[2] = zg; o[3] = wg; o[4] = lg; o[5] = hg; o[6] = rg;

        float cc = fabsf(cosf(rg)), ss = fabsf(sinf(rg));
        float hx = 0.5f * (wg * cc + lg * ss);
        float hy = 0.5f * (wg * ss + lg * cc);
        bb = make_float4(xg - hx, yg - hy, xg + hx, yg + hy);

        size_t dbase = ((size_t)b * NN + idx) * 2;
        dl = (dirp[dbase + 1] > dirp[dbase + 0]) ? 1 : 0;

        atomicOr(&g_validmask[b * WPB + (r >> 6)], 1ull << (r & 63));
    }
#pragma unroll
    for (int j = 0; j < 7; ++j) g_boxes[(size_t)i * 7 + j] = o[j];
    g_bb4[i] = bb;
    g_dl[i]  = dl;
}

// ---------------- 8) pairwise IoU bit-matrix (upper triangle, ballot) -------
__global__ void __launch_bounds__(256) iou_kernel() {
    int p = blockIdx.x;          // triangular pair index [0, 528)
    int b = blockIdx.y;
    int rb = (int)((65.0f - sqrtf(4225.0f - 8.0f * (float)p)) * 0.5f);
    while (rb * (65 - rb) / 2 > p) --rb;
    while ((rb + 1) * (64 - rb) / 2 <= p) ++rb;
    int cb = rb + (p - rb * (65 - rb) / 2);

    int t = threadIdx.x;
    __shared__ float4 scol[64]; __shared__ float sca[64];
    __shared__ float4 srow[64]; __shared__ float sra[64];
    if (t < 64) {
        float4 c = g_bb4[(size_t)b * PRE + cb * 64 + t];
        scol[t] = c; sca[t] = (c.z - c.x) * (c.w - c.y);
    } else if (t < 128) {
        int r = t - 64;
        float4 c = g_bb4[(size_t)b * PRE + rb * 64 + r];
        srow[r] = c; sra[r] = (c.z - c.x) * (c.w - c.y);
    }
    __syncthreads();

    int wid = t >> 5, lane = t & 31;
#pragma unroll
    for (int rr = 0; rr < 8; ++rr) {
        int r = wid * 8 + rr;
        int grow = rb * 64 + r;
        float4 rbx = srow[r];
        float  ra  = sra[r];
        unsigned long long bits = 0ull;
#pragma unroll
        for (int h = 0; h < 2; ++h) {
            int c = h * 32 + lane;
            int gcol = cb * 64 + c;
            float4 cc = scol[c];
            float ix = fmaxf(0.f, fminf(rbx.z, cc.z) - fmaxf(rbx.x, cc.x));
            float iy = fmaxf(0.f, fminf(rbx.w, cc.w) - fmaxf(rbx.y, cc.y));
            float inter = ix * iy;
            float denom = fmaxf(ra + sca[c] - inter, 1e-8f);
            bool sup = (gcol > grow) && (inter > 0.5f * denom);
            unsigned m = __ballot_sync(0xFFFFFFFFu, sup);
            bits |= (unsigned long long)m << (h * 32);
        }
        if (lane == 0)
            g_supmask[((size_t)b * PRE + grow) * WPB + cb] = bits;
    }
}

// ---------------- 9) greedy NMS (smem-staged, double-buffered) --------------
__global__ void __launch_bounds__(128) nms_kernel() {
    int b = blockIdx.x, tid = threadIdx.x;
    __shared__ unsigned long long s_rows[2][64][WPB];   // 2 x 16KB
    int lane = tid & 31;
    unsigned long long remv = 0ull, myvalid = 0ull;
    if (tid < 32) myvalid = g_validmask[b * WPB + tid];

    for (int idx = tid; idx < 64 * WPB; idx += 128) {
        int r = idx >> 5, w = idx & 31;
        s_rows[0][r][w] = g_supmask[((size_t)b * PRE + r) * WPB + w];
    }
    __syncthreads();

    for (int chunk = 0; chunk < WPB; ++chunk) {
        int cur = chunk & 1;
        if (tid >= 32 && chunk + 1 < WPB) {          // warps 1-3 prefetch next
            int base = (chunk + 1) * 64;
            for (int idx = tid - 32; idx < 64 * WPB; idx += 96) {
                int r = idx >> 5, w = idx & 31;
                s_rows[cur ^ 1][r][w] = g_supmask[((size_t)b * PRE + base + r) * WPB + w];
            }
        }
        if (tid < 32) {
            unsigned long long alive = 0ull;
            if (lane == chunk) {
                unsigned long long w = remv, vw = myvalid;
#pragma unroll
                for (int g = 0; g < 4; ++g) {
                    unsigned long long sd[16];
#pragma unroll
                    for (int j = 0; j < 16; ++j) sd[j] = s_rows[cur][g * 16 + j][chunk];
#pragma unroll
                    for (int j = 0; j < 16; ++j) {
                        unsigned long long bit = 1ull << (g * 16 + j);
                        if ((vw & bit) && !(w & bit)) { alive |= bit; w |= sd[j]; }
                    }
                }
                remv = w;
                g_keepmask[b * WPB + chunk] = alive;
            }
            alive = __shfl_sync(0xFFFFFFFFu, alive, chunk);
            if (lane > chunk) {
                unsigned long long m = alive;
                while (m) {
                    int r = __ffsll((long long)m) - 1;
                    m &= m - 1;
                    remv |= s_rows[cur][r][lane];
                }
            }
        }
        __syncthreads();
    }
}

// ---------------- 10) final top-128 + dir rotation + range mask -------------
__global__ void out_kernel(float* __restrict__ out) {
    int b = blockIdx.x;
    int t = threadIdx.x;
    __shared__ int sel[POST];
    __shared__ int s_cnt;

    if (t == 0) {
        int cnt = 0;
        for (int w = 0; w < WPB && cnt < POST; ++w) {
            unsigned long long m = g_keepmask[b * WPB + w];
            while (m && cnt < POST) {
                int r = __ffsll((long long)m) - 1;
                m &= m - 1;
                sel[cnt++] = w * 64 + r;
            }
        }
        s_cnt = cnt;
    }
    __syncthreads();

    float o0 = 0.f, o1 = 0.f, o2 = 0.f, o3 = 0.f, o4 = 0.f, o5 = 0.f, o6 = 0.f;
    float os = 0.f, om = 0.f;
    if (t < s_cnt) {
        int r = sel[t];
        const float* bx = &g_boxes[((size_t)b * PRE + r) * 7];
        float x = bx[0], y = bx[1], z = bx[2];
        float w = bx[3], l = bx[4], h = bx[5], rg = bx[6];
        float score = __uint_as_float((unsigned)(g_topkeys[(size_t)b * PRE + r] >> 32));
        int dl = g_dl[b * PRE + r];
        const float period = 3.14159265358979323846f;   // 2*pi/NUM_DIR_BINS
        float dir_rot = rg - floorf(rg / period) * period;
        float new_r = dir_rot + period * (float)dl;
        bool in_range = (x >= 0.0f) && (y >= -39.68f) && (z >= -5.0f) &&
                        (x <= 69.12f) && (y <= 39.68f) && (z <= 5.0f);
        if (in_range) {
            o0 = x; o1 = y; o2 = z; o3 = w; o4 = l; o5 = h; o6 = new_r;
            os = score; om = 1.0f;
        }
    }
    size_t bo = (size_t)b * POST + t;
    out[bo * 7 + 0] = o0; out[bo * 7 + 1] = o1; out[bo * 7 + 2] = o2;
    out[bo * 7 + 3] = o3; out[bo * 7 + 4] = o4; out[bo * 7 + 5] = o5;
    out[bo * 7 + 6] = o6;
    out[BB * POST * 7 + bo]                 = os;   // scores
    out[BB * POST * 7 + BB * POST + bo]     = 0.0f; // labels
    out[BB * POST * 7 + 2 * BB * POST + bo] = om;   // mask
}

// ---------------- launcher ----------------
extern "C" void kernel_launch(void* const* d_in, const int* in_sizes, int n_in,
                              void* d_out, int out_size) {
    const float* boxp = (const float*)d_in[0];   // (B,N,7)
    const float* clsp = (const float*)d_in[1];   // (B,N,2)
    const float* dirp = (const float*)d_in[2];   // (B,N,2)
    const float* anch = (const float*)d_in[3];   // (B,N,7)
    float* out = (float*)d_out;

    zero_kernel<<<(BB * HB + 255) / 256, 256>>>();
    score_hist_kernel<<<(BB * NN + 255) / 256, 256>>>((const float2*)clsp);
    scan1_kernel<<<BB, 1024>>>();
    hist2_kernel<<<(BB * NN + 255) / 256, 256>>>();
    scan2_kernel<<<BB, 1024>>>();
    compact_kernel<<<(BB * NN + 255) / 256, 256>>>();
    dim3 grank(CAND / 256, BB);
    rank_kernel<<<grank, 256>>>();
    decode_kernel<<<(BB * PRE + 127) / 128, 128>>>(boxp, dirp, anch);
    dim3 giou(528, BB);
    iou_kernel<<<giou, 256>>>();
    nms_kernel<<<BB, 128>>>();
    out_kernel<<<BB, POST>>>(out);
}

// round 4
// speedup vs baseline: 1.2519x; 1.2519x over previous
#include <cuda_runtime.h>
#include <math.h>

#define BB   8
#define NN   107136
#define PRE  2048
#define POST 128
#define CAND 6144    // 48KB smem in rank kernel; actual candidates ~2700
#define WPB  32      // 64-bit words per row mask (PRE/64)
#define HB   65536   // 16-bit histogram bins

// ---------------- scratch (static __device__, no allocations) ----------------
static __device__ unsigned int       g_skey[BB * NN];
static __device__ unsigned int       g_hist16[BB * HB];
static __device__ unsigned int       g_thresh[BB];
static __device__ unsigned long long g_cand[BB * CAND];
static __device__ int                g_cand_cnt[BB];
static __device__ unsigned long long g_topkeys[BB * PRE];
static __device__ float              g_boxes[BB * PRE * 7];
static __device__ float4             g_bb4[BB * PRE];
static __device__ int                g_dl[BB * PRE];
static __device__ unsigned long long g_supmask[(size_t)BB * PRE * WPB];
static __device__ unsigned long long g_validmask[BB * WPB];

// ---------------- 0) zero scratch ----------------
__global__ void zero_kernel() {
    int i = blockIdx.x * blockDim.x + threadIdx.x;
    if (i < BB * HB / 4) ((uint4*)g_hist16)[i] = make_uint4(0u, 0u, 0u, 0u);
    if (i < BB) { g_cand_cnt[i] = 0; g_thresh[i] = 1u; }   // thresh=1: take-all fallback
    if (i < BB * WPB) g_validmask[i] = 0ull;
    if (i < BB * PRE) g_topkeys[i] = 0ull;
}

// ---------------- 1) scores -> keys + 16-bit histogram (2 elems/thread) -----
__global__ void score_hist_kernel(const float4* __restrict__ cls) {
    int i = blockIdx.x * blockDim.x + threadIdx.x;   // pair index
    if (i >= BB * NN / 2) return;
    int b = (2 * i) / NN;
    float4 c = cls[i];
    // element 2i : logits (c.x, c.y) ; element 2i+1 : logits (c.z, c.w)
    float m0 = fmaxf(c.x, c.y);
    float p0 = expf(c.y - m0) / (expf(c.x - m0) + expf(c.y - m0));
    float m1 = fmaxf(c.z, c.w);
    float p1 = expf(c.w - m1) / (expf(c.z - m1) + expf(c.w - m1));
    unsigned int k0 = (p0 >= 0.05f) ? __float_as_uint(p0) : 0u;
    unsigned int k1 = (p1 >= 0.05f) ? __float_as_uint(p1) : 0u;
    ((uint2*)g_skey)[i] = make_uint2(k0, k1);
    if (k0) atomicAdd(&g_hist16[b * HB + (k0 >> 16)], 1u);
    if (k1) atomicAdd(&g_hist16[b * HB + (k1 >> 16)], 1u);
}

// ---------------- 2) parallel crossing-bin search (suffix scan) -------------
__global__ void __launch_bounds__(1024) scan_kernel() {
    int b = blockIdx.x, tid = threadIdx.x;
    int lane = tid & 31, wid = tid >> 5;
    __shared__ unsigned wsum[32];
    __shared__ unsigned wsuf[32];
    const uint4* h4 = (const uint4*)(g_hist16 + b * HB);

    // streaming sum of my 64 bins (16 uint4, contiguous 256B block)
    unsigned tsum = 0;
#pragma unroll
    for (int j = 0; j < 16; ++j) {
        uint4 v = h4[tid * 16 + j];
        tsum += v.x + v.y + v.z + v.w;
    }
    // inclusive suffix scan within warp (sum over lanes >= mine)
    unsigned s = tsum;
#pragma unroll
    for (int off = 1; off < 32; off <<= 1) {
        unsigned o = __shfl_down_sync(0xFFFFFFFFu, s, off);
        if (lane + off < 32) s += o;
    }
    if (lane == 0) wsum[wid] = s;    // warp total
    __syncthreads();
    if (tid < 32) {
        unsigned t = wsum[tid];
        unsigned e = t;
#pragma unroll
        for (int off = 1; off < 32; off <<= 1) {
            unsigned o = __shfl_down_sync(0xFFFFFFFFu, e, off);
            if (tid + off < 32) e += o;
        }
        wsuf[tid] = e - t;           // sum of warps strictly above
    }
    __syncthreads();
    unsigned above = wsuf[wid] + (s - tsum);   // keys in bins above my 64
    if (above < PRE && above + tsum >= PRE) {  // unique crossing thread
        unsigned run = above;
        int found = -1;
        for (int j = 15; j >= 0 && found < 0; --j) {
            uint4 v = h4[tid * 16 + j];
            unsigned a[4] = {v.x, v.y, v.z, v.w};
            for (int q = 3; q >= 0; --q) {
                if (run + a[q] >= PRE) { found = tid * 64 + j * 4 + q; break; }
                run += a[q];
            }
        }
        g_thresh[b] = ((unsigned)found) << 16;  // 16-bit bin floor threshold
    }
}

// ---------------- 3) compact candidates (vec4 + warp-aggregated atomic) -----
__global__ void compact_kernel() {
    int i4 = blockIdx.x * blockDim.x + threadIdx.x;  // [0, BB*NN/4)
    if (i4 >= BB * NN / 4) return;
    int e0 = i4 * 4;
    int b = e0 / NN;                  // NN % 128 == 0 -> warp-uniform b
    unsigned thresh = g_thresh[b];
    uint4 kv = ((const uint4*)g_skey)[i4];
    unsigned k[4] = {kv.x, kv.y, kv.z, kv.w};
    unsigned long long loc[4]; int nh = 0;
    unsigned base_i = (unsigned)(e0 - b * NN);
#pragma unroll
    for (int q = 0; q < 4; ++q) {
        if (k[q] && k[q] >= thresh)
            loc[nh++] = ((unsigned long long)k[q] << 32) |
                        (unsigned long long)(0xFFFFFFFFu - (base_i + q));
    }
    int lane = threadIdx.x & 31;
    int pre = nh;
#pragma unroll
    for (int off = 1; off < 32; off <<= 1) {
        int o = __shfl_up_sync(0xFFFFFFFFu, pre, off);
        if (lane >= off) pre += o;
    }
    int tot = __shfl_sync(0xFFFFFFFFu, pre, 31);
    pre -= nh;
    int base = 0;
    if (lane == 31 && tot > 0) base = atomicAdd(&g_cand_cnt[b], tot);
    base = __shfl_sync(0xFFFFFFFFu, base, 31);
    for (int q = 0; q < nh; ++q) {
        int p = base + pre + q;
        if (p < CAND) g_cand[b * CAND + p] = loc[q];
    }
}

// ---------------- 4) rank-scatter: exact top-2048 order ----------------
__global__ void __launch_bounds__(256) rank_kernel() {
    int b = blockIdx.y, tid = threadIdx.x;
    __shared__ unsigned long long sk[CAND];   // 48KB
    __shared__ int scnt;
    if (tid == 0) { int c = g_cand_cnt[b]; scnt = (c > CAND) ? CAND : c; }
    __syncthreads();
    int cnt = scnt;
    for (int i = tid; i < cnt; i += 256) sk[i] = g_cand[b * CAND + i];
    __syncthreads();
    int i = blockIdx.x * 256 + tid;
    if (i >= cnt) return;
    unsigned long long mine = sk[i];
    int rank = 0, j = 0;
    for (; j + 4 <= cnt; j += 4) {
        rank += (sk[j]     > mine);
        rank += (sk[j + 1] > mine);
        rank += (sk[j + 2] > mine);
        rank += (sk[j + 3] > mine);
    }
    for (; j < cnt; ++j) rank += (sk[j] > mine);
    if (rank < PRE) g_topkeys[(size_t)b * PRE + rank] = mine;
}

// ---------------- 5) decode selected boxes ----------------
__global__ void decode_kernel(const float* __restrict__ boxp,
                              const float* __restrict__ dirp,
                              const float* __restrict__ anch) {
    int i = blockIdx.x * blockDim.x + threadIdx.x;
    if (i >= BB * PRE) return;
    int b = i / PRE, r = i % PRE;
    unsigned long long key = g_topkeys[i];
    unsigned int skey = (unsigned)(key >> 32);

    float o[7] = {0.f, 0.f, 0.f, 0.f, 0.f, 0.f, 0.f};
    float4 bb  = make_float4(0.f, 0.f, 0.f, 0.f);
    int dl = 0;

    if (skey) {
        unsigned idx = 0xFFFFFFFFu - (unsigned)(key & 0xFFFFFFFFull);
        size_t base = ((size_t)b * NN + idx) * 7;
        float xa = anch[base + 0], ya = anch[base + 1], za = anch[base + 2];
        float wa = anch[base + 3], la = anch[base + 4], ha = anch[base + 5];
        float ra = anch[base + 6];
        float xt = boxp[base + 0], yt = boxp[base + 1], zt = boxp[base + 2];
        float wt = boxp[base + 3], lt = boxp[base + 4], ht = boxp[base + 5];
        float rt = boxp[base + 6];

        za = za + ha * 0.5f;
        float diag = sqrtf(la * la + wa * wa);
        float xg = xt * diag + xa;
        float yg = yt * diag + ya;
        float zg = zt * ha + za;
        float lg = expf(lt) * la;
        float wg = expf(wt) * wa;
        float hg = expf(ht) * ha;
        float rg = rt + ra;
        zg = zg - hg * 0.5f;

        o[0] = xg; o[1] = yg; o[2] = zg; o[3] = wg; o[4] = lg; o[5] = hg; o[6] = rg;

        float cc = fabsf(cosf(rg)), ss = fabsf(sinf(rg));
        float hx = 0.5f * (wg * cc + lg * ss);
        float hy = 0.5f * (wg * ss + lg * cc);
        bb = make_float4(xg - hx, yg - hy, xg + hx, yg + hy);

        size_t dbase = ((size_t)b * NN + idx) * 2;
        dl = (dirp[dbase + 1] > dirp[dbase + 0]) ? 1 : 0;

        atomicOr(&g_validmask[b * WPB + (r >> 6)], 1ull << (r & 63));
    }
#pragma unroll
    for (int j = 0; j < 7; ++j) g_boxes[(size_t)i * 7 + j] = o[j];
    g_bb4[i] = bb;
    g_dl[i]  = dl;
}

// ---------------- 6) pairwise IoU bit-matrix (upper triangle, ballot) -------
__global__ void __launch_bounds__(256) iou_kernel() {
    int p = blockIdx.x;          // triangular pair index [0, 528)
    int b = blockIdx.y;
    int rb = (int)((65.0f - sqrtf(4225.0f - 8.0f * (float)p)) * 0.5f);
    while (rb * (65 - rb) / 2 > p) --rb;
    while ((rb + 1) * (64 - rb) / 2 <= p) ++rb;
    int cb = rb + (p - rb * (65 - rb) / 2);

    int t = threadIdx.x;
    __shared__ float4 scol[64]; __shared__ float sca[64];
    __shared__ float4 srow[64]; __shared__ float sra[64];
    if (t < 64) {
        float4 c = g_bb4[(size_t)b * PRE + cb * 64 + t];
        scol[t] = c; sca[t] = (c.z - c.x) * (c.w - c.y);
    } else if (t < 128) {
        int r = t - 64;
        float4 c = g_bb4[(size_t)b * PRE + rb * 64 + r];
        srow[r] = c; sra[r] = (c.z - c.x) * (c.w - c.y);
    }
    __syncthreads();

    int wid = t >> 5, lane = t & 31;
#pragma unroll
    for (int rr = 0; rr < 8; ++rr) {
        int r = wid * 8 + rr;
        int grow = rb * 64 + r;
        float4 rbx = srow[r];
        float  ra  = sra[r];
        unsigned long long bits = 0ull;
#pragma unroll
        for (int h = 0; h < 2; ++h) {
            int c = h * 32 + lane;
            int gcol = cb * 64 + c;
            float4 cc = scol[c];
            float ix = fmaxf(0.f, fminf(rbx.z, cc.z) - fmaxf(rbx.x, cc.x));
            float iy = fmaxf(0.f, fminf(rbx.w, cc.w) - fmaxf(rbx.y, cc.y));
            float inter = ix * iy;
            float denom = fmaxf(ra + sca[c] - inter, 1e-8f);
            bool sup = (gcol > grow) && (inter > 0.5f * denom);
            unsigned m = __ballot_sync(0xFFFFFFFFu, sup);
            bits |= (unsigned long long)m << (h * 32);
        }
        if (lane == 0)
            g_supmask[((size_t)b * PRE + grow) * WPB + cb] = bits;
    }
}

// ---------------- 7) greedy NMS + final output (fused) ----------------
__global__ void __launch_bounds__(128) nms_out_kernel(float* __restrict__ out) {
    int b = blockIdx.x, tid = threadIdx.x;
    __shared__ unsigned long long s_rows[2][64][WPB];   // 2 x 16KB
    __shared__ unsigned long long s_keep[WPB];
    __shared__ int sel[POST];
    __shared__ int s_cnt;
    int lane = tid & 31;
    unsigned long long remv = 0ull, myvalid = 0ull;
    if (tid < 32) myvalid = g_validmask[b * WPB + tid];

    for (int idx = tid; idx < 64 * WPB; idx += 128) {
        int r = idx >> 5, w = idx & 31;
        s_rows[0][r][w] = g_supmask[((size_t)b * PRE + r) * WPB + w];
    }
    __syncthreads();

    for (int chunk = 0; chunk < WPB; ++chunk) {
        int cur = chunk & 1;
        if (tid >= 32 && chunk + 1 < WPB) {          // warps 1-3 prefetch next
            int base = (chunk + 1) * 64;
            for (int idx = tid - 32; idx < 64 * WPB; idx += 96) {
                int r = idx >> 5, w = idx & 31;
                s_rows[cur ^ 1][r][w] = g_supmask[((size_t)b * PRE + base + r) * WPB + w];
            }
        }
        if (tid < 32) {
            unsigned long long alive = 0ull;
            if (lane == chunk) {
                unsigned long long w = remv, vw = myvalid;
#pragma unroll
                for (int g = 0; g < 4; ++g) {
                    unsigned long long sd[16];
#pragma unroll
                    for (int j = 0; j < 16; ++j) sd[j] = s_rows[cur][g * 16 + j][chunk];
#pragma unroll
                    for (int j = 0; j < 16; ++j) {
                        unsigned long long bit = 1ull << (g * 16 + j);
                        if ((vw & bit) && !(w & bit)) { alive |= bit; w |= sd[j]; }
                    }
                }
                remv = w;
                s_keep[chunk] = alive;
            }
            alive = __shfl_sync(0xFFFFFFFFu, alive, chunk);
            if (lane > chunk) {
                unsigned long long m = alive;
                while (m) {
                    int r = __ffsll((long long)m) - 1;
                    m &= m - 1;
                    remv |= s_rows[cur][r][lane];
                }
            }
        }
        __syncthreads();
    }

    // ---- fused output phase (block == 128 == POST threads) ----
    if (tid == 0) {
        int cnt = 0;
        for (int w = 0; w < WPB && cnt < POST; ++w) {
            unsigned long long m = s_keep[w];
            while (m && cnt < POST) {
                int r = __ffsll((long long)m) - 1;
                m &= m - 1;
                sel[cnt++] = w * 64 + r;
            }
        }
        s_cnt = cnt;
    }
    __syncthreads();

    float o0 = 0.f, o1 = 0.f, o2 = 0.f, o3 = 0.f, o4 = 0.f, o5 = 0.f, o6 = 0.f;
    float os = 0.f, om = 0.f;
    if (tid < s_cnt) {
        int r = sel[tid];
        const float* bx = &g_boxes[((size_t)b * PRE + r) * 7];
        float x = bx[0], y = bx[1], z = bx[2];
        float w = bx[3], l = bx[4], h = bx[5], rg = bx[6];
        float score = __uint_as_float((unsigned)(g_topkeys[(size_t)b * PRE + r] >> 32));
        int dl = g_dl[b * PRE + r];
        const float period = 3.14159265358979323846f;   // 2*pi/NUM_DIR_BINS
        float dir_rot = rg - floorf(rg / period) * period;
        float new_r = dir_rot + period * (float)dl;
        bool in_range = (x >= 0.0f) && (y >= -39.68f) && (z >= -5.0f) &&
                        (x <= 69.12f) && (y <= 39.68f) && (z <= 5.0f);
        if (in_range) {
            o0 = x; o1 = y; o2 = z; o3 = w; o4 = l; o5 = h; o6 = new_r;
            os = score; om = 1.0f;
        }
    }
    size_t bo = (size_t)b * POST + tid;
    out[bo * 7 + 0] = o0; out[bo * 7 + 1] = o1; out[bo * 7 + 2] = o2;
    out[bo * 7 + 3] = o3; out[bo * 7 + 4] = o4; out[bo * 7 + 5] = o5;
    out[bo * 7 + 6] = o6;
    out[BB * POST * 7 + bo]                 = os;   // scores
    out[BB * POST * 7 + BB * POST + bo]     = 0.0f; // labels
    out[BB * POST * 7 + 2 * BB * POST + bo] = om;   // mask
}

// ---------------- launcher ----------------
extern "C" void kernel_launch(void* const* d_in, const int* in_sizes, int n_in,
                              void* d_out, int out_size) {
    const float* boxp = (const float*)d_in[0];   // (B,N,7)
    const float* clsp = (const float*)d_in[1];   // (B,N,2)
    const float* dirp = (const float*)d_in[2];   // (B,N,2)
    const float* anch = (const float*)d_in[3];   // (B,N,7)
    float* out = (float*)d_out;

    zero_kernel<<<(BB * HB / 4 + 255) / 256, 256>>>();
    score_hist_kernel<<<(BB * NN / 2 + 255) / 256, 256>>>((const float4*)clsp);
    scan_kernel<<<BB, 1024>>>();
    compact_kernel<<<(BB * NN / 4 + 255) / 256, 256>>>();
    dim3 grank((CAND + 255) / 256, BB);
    rank_kernel<<<grank, 256>>>();
    decode_kernel<<<(BB * PRE + 127) / 128, 128>>>(boxp, dirp, anch);
    dim3 giou(528, BB);
    iou_kernel<<<giou, 256>>>();
    nms_out_kernel<<<BB, 128>>>(out);
}